// round 6
// baseline (speedup 1.0000x reference)
#include <cuda_runtime.h>
#include <cuda_bf16.h>

#define BATCH 16
#define NPTS  8192
#define NSAMP 4096
#define THREADS 512
#define PPT 16            // points per thread = NPTS / THREADS
#define NPAIR (PPT / 2)
#define NWARP (THREADS / 32)

typedef unsigned long long u64;

__device__ int g_idx[BATCH * NSAMP];

// ---------- packed f32x2 helpers (per-lane IEEE rn => bit-identical to scalar) ----------
__device__ __forceinline__ u64 pack2(float lo, float hi) {
    u64 r; asm("mov.b64 %0, {%1, %2};" : "=l"(r) : "f"(lo), "f"(hi)); return r;
}
__device__ __forceinline__ void unpack2(u64 v, float& lo, float& hi) {
    asm("mov.b64 {%0, %1}, %2;" : "=f"(lo), "=f"(hi) : "l"(v));
}
__device__ __forceinline__ u64 add2(u64 a, u64 b) {
    u64 r; asm("add.rn.f32x2 %0, %1, %2;" : "=l"(r) : "l"(a), "l"(b)); return r;
}
__device__ __forceinline__ u64 mul2(u64 a, u64 b) {
    u64 r; asm("mul.rn.f32x2 %0, %1, %2;" : "=l"(r) : "l"(a), "l"(b)); return r;
}
__device__ __forceinline__ u64 fma2(u64 a, u64 b, u64 c) {
    u64 r; asm("fma.rn.f32x2 %0, %1, %2, %3;" : "=l"(r) : "l"(a), "l"(b), "l"(c)); return r;
}
__device__ __forceinline__ unsigned redux_max_u32(unsigned v) {
    unsigned r; asm("redux.sync.max.u32 %0, %1, 0xffffffff;" : "=r"(r) : "r"(v)); return r;
}
__device__ __forceinline__ unsigned redux_min_u32(unsigned v) {
    unsigned r; asm("redux.sync.min.u32 %0, %1, 0xffffffff;" : "=r"(r) : "r"(v)); return r;
}

// Pre-negated, pre-replicated centroid components.
// negxy[i] = { {-x,-x}, {-y,-y} } (16B, one LDS.128 broadcast)
// negz[i]  = { -z,-z }            (8B,  one LDS.64  broadcast)
struct NegXY { u64 x2, y2; };

struct SmemLayout {
    NegXY negxy[NPTS];       // 128 KB
    u64   negz[NPTS];        //  64 KB
    u64   key[2][NWARP];     // double-buffered per-warp argmax keys (dist_bits<<32 | idx)
};

__global__ __launch_bounds__(THREADS, 1)
void fps_kernel(const float* __restrict__ coords, const int* __restrict__ init_farthest)
{
    extern __shared__ char raw[];
    SmemLayout* sm = reinterpret_cast<SmemLayout*>(raw);

    const int b = blockIdx.x;
    const int t = threadIdx.x;
    const int base = t * PPT;
    const float* cb = coords + (size_t)b * NPTS * 3;

    // ---- init: registers hold positive coords (packed); smem holds negated replicated ----
    float lx[PPT], ly[PPT], lz[PPT];
#pragma unroll
    for (int j = 0; j < PPT; j++) {
        const int idx = base + j;
        lx[j] = cb[idx * 3 + 0];
        ly[j] = cb[idx * 3 + 1];
        lz[j] = cb[idx * 3 + 2];
        sm->negxy[idx].x2 = pack2(-lx[j], -lx[j]);
        sm->negxy[idx].y2 = pack2(-ly[j], -ly[j]);
        sm->negz[idx]     = pack2(-lz[j], -lz[j]);
    }
    u64 PX[NPAIR], PY[NPAIR], PZ[NPAIR];
    float dist[PPT];
#pragma unroll
    for (int p = 0; p < NPAIR; p++) {
        PX[p] = pack2(lx[2 * p], lx[2 * p + 1]);
        PY[p] = pack2(ly[2 * p], ly[2 * p + 1]);
        PZ[p] = pack2(lz[2 * p], lz[2 * p + 1]);
    }
#pragma unroll
    for (int j = 0; j < PPT; j++) dist[j] = 1e8f;   // INIT_DIST

    int f = init_farthest[b];
    __syncthreads();

    int* gout = g_idx + b * NSAMP;
    const int lane = t & 31;
    const int w = t >> 5;
    int par = 0;

    for (int s = 0; s < NSAMP; s++) {
        if (t == 0) gout[s] = f;   // record current farthest (record then update)

        const u64 ncx = sm->negxy[f].x2;     // LDS.128 broadcast (x2,y2 contiguous)
        const u64 ncy = sm->negxy[f].y2;
        const u64 ncz = sm->negz[f];         // LDS.64 broadcast

        float bd = -1.0f;
        float pm[NPAIR];
#pragma unroll
        for (int p = 0; p < NPAIR; p++) {
            u64 dx = add2(PX[p], ncx);       // px + (-cx) == px - cx (exact)
            u64 dy = add2(PY[p], ncy);
            u64 dz = add2(PZ[p], ncz);
            // per-lane d = fma(dz,dz, fma(dy,dy, dx*dx)) — matches XLA contracted reduce
            u64 d2 = fma2(dz, dz, fma2(dy, dy, mul2(dx, dx)));
            float d0, d1; unpack2(d2, d0, d1);
            float n0 = fminf(dist[2 * p], d0);
            float n1 = fminf(dist[2 * p + 1], d1);
            dist[2 * p] = n0;
            dist[2 * p + 1] = n1;
            pm[p] = fmaxf(n0, n1);
            bd = fmaxf(bd, pm[p]);
        }
        // lowest local index achieving bd: reverse scan over pairs, then within pair
        int bp = 0;
#pragma unroll
        for (int p = NPAIR - 1; p >= 0; p--) if (pm[p] == bd) bp = p;
        const int bj = 2 * bp + ((dist[2 * bp] == bd) ? 0 : 1);
        const int bi = base + bj;

        // warp argmax: dists >= 0 so float order == uint order on the bits
        const unsigned vb = __float_as_uint(bd);
        const unsigned wmax = redux_max_u32(vb);
        const unsigned cand = (vb == wmax) ? (unsigned)bi : 0xFFFFFFFFu;
        const unsigned wbi = redux_min_u32(cand);

        if (lane == 0)
            sm->key[par][w] = ((u64)wmax << 32) | (u64)wbi;
        __syncthreads();

        // stage 2: every warp redundantly reduces the 16 per-warp keys
        const u64 k = sm->key[par][lane & (NWARP - 1)];
        const unsigned kd = (unsigned)(k >> 32);
        const unsigned ki = (unsigned)k;
        const unsigned gmax = redux_max_u32(kd);
        const unsigned gc = (kd == gmax) ? ki : 0xFFFFFFFFu;
        f = (int)redux_min_u32(gc);

        par ^= 1;   // double-buffer: next iter's writes can't race this iter's reads
    }
}

// Output layout: [B,S,3] coords | [B,S,128] values | [B,S] mask, all fp32, concatenated.
__global__ void gather_kernel(const float* __restrict__ coords,
                              const float* __restrict__ values,
                              const float* __restrict__ mask,
                              float* __restrict__ out)
{
    const int V4 = BATCH * NSAMP * 32;   // float4 chunks of values output
    int i = blockIdx.x * blockDim.x + threadIdx.x;

    float* out_coords = out;
    float* out_vals   = out + (size_t)BATCH * NSAMP * 3;
    float* out_mask   = out + (size_t)BATCH * NSAMP * (3 + 128);

    if (i < V4) {
        const int c4 = i & 31;
        const int bs = i >> 5;
        const int b  = bs >> 12;
        const int s  = bs & (NSAMP - 1);
        const int idx = g_idx[b * NSAMP + s];
        const float4 v = reinterpret_cast<const float4*>(values)
                             [((size_t)b * NPTS + idx) * 32 + c4];
        reinterpret_cast<float4*>(out_vals)[(size_t)bs * 32 + c4] = v;
    } else if (i < V4 + BATCH * NSAMP) {
        const int bs = i - V4;
        const int b  = bs >> 12;
        const int s  = bs & (NSAMP - 1);
        const int idx = g_idx[b * NSAMP + s];
        const size_t src = (size_t)b * NPTS + idx;
        out_coords[bs * 3 + 0] = coords[src * 3 + 0];
        out_coords[bs * 3 + 1] = coords[src * 3 + 1];
        out_coords[bs * 3 + 2] = coords[src * 3 + 2];
        out_mask[bs] = mask[src];
    }
}

extern "C" void kernel_launch(void* const* d_in, const int* in_sizes, int n_in,
                              void* d_out, int out_size)
{
    const float* coords = (const float*)d_in[0];
    const float* values = (const float*)d_in[1];
    const float* mask   = (const float*)d_in[2];
    const int*   initf  = (const int*)d_in[3];
    float* out = (float*)d_out;

    const int smem = sizeof(SmemLayout);
    cudaFuncSetAttribute(fps_kernel, cudaFuncAttributeMaxDynamicSharedMemorySize, smem);

    fps_kernel<<<BATCH, THREADS, smem>>>(coords, initf);

    const int total = BATCH * NSAMP * 32 + BATCH * NSAMP;
    gather_kernel<<<(total + 255) / 256, 256>>>(coords, values, mask, out);
}